// round 13
// baseline (speedup 1.0000x reference)
#include <cuda_runtime.h>

// Problem constants (fixed-shape problem)
#define NVOC 100     // vocab
#define NL   5       // gate layers
#define NH   32      // gate hidden (== warp size)
#define NSD  16      // s-dim
#define NG   8192    // segments
#define NEMB 128     // embedding dim
#define NHID 64      // EMB/2

// Scratch (__device__ globals; no allocations allowed).
// Both are fully rewritten every replay -> deterministic.
__device__ float g_F[NVOC * NHID];      // F[v] = scale[v] * (emb[v] @ pw1)
__device__ int   g_segstart[NG + 1];    // lower_bound of g in sorted batch

// ---------------------------------------------------------------------------
// Kernel 1 (fused, independent block ranges):
//   blocks [0, nbb)        : segment boundaries from sorted batch
//   blocks [nbb, nbb+NVOC) : F[v][j] = scale[v] * (emb[v] . pw1[:,j])
// ---------------------------------------------------------------------------
__global__ void __launch_bounds__(256)
prep_kernel(const int* __restrict__ batch,
            const float* __restrict__ emb, const float* __restrict__ w1,
            const float* __restrict__ b1,  const float* __restrict__ w2,
            const float* __restrict__ b2,  const float* __restrict__ pw1,
            int N, int nbb) {
    int bid = blockIdx.x;
    if (bid < nbb) {
        // ---- boundaries: seg_start[g] = first i with batch[i] >= g --------
        int i0 = (bid * 256 + threadIdx.x) * 4;   // this thread's 4 nodes
        if (i0 >= N) return;
        int b[5];
        if (i0 + 4 <= N) {
            int4 q = *reinterpret_cast<const int4*>(batch + i0);
            b[0] = q.x; b[1] = q.y; b[2] = q.z; b[3] = q.w;
        } else {
#pragma unroll
            for (int k = 0; k < 4; k++)
                b[k] = (i0 + k < N) ? batch[i0 + k] : 0;
        }
        b[4] = (i0 + 4 < N) ? batch[i0 + 4] : NG;   // sentinel past the end

        if (i0 == 0)
            for (int g = 0; g <= b[0]; g++) g_segstart[g] = 0;
#pragma unroll
        for (int k = 0; k < 4; k++) {
            if (i0 + k >= N) break;
            for (int g = b[k] + 1; g <= b[k + 1]; g++)
                g_segstart[g] = i0 + k + 1;
        }
    } else {
        // ---- F row for vocab v --------------------------------------------
        int v = bid - nbb;
        __shared__ float e1s[NHID];
        __shared__ float s_scale;
        int tid = threadIdx.x;

        if (tid < NHID) {                       // E1[v][j] = emb[v] . pw1[:,j]
            float a = 0.f;
#pragma unroll 8
            for (int d = 0; d < NEMB; d++)
                a = fmaf(emb[v * NEMB + d], pw1[d * NHID + tid], a);
            e1s[tid] = a;
        }
        if (tid < 32) {                         // gate cascade (vocab-only)
            float e[NSD];
#pragma unroll
            for (int k = 0; k < NSD; k++) e[k] = emb[v * NEMB + k];
            float scale = 1.f;
#pragma unroll
            for (int l = 0; l < NL; l++) {
                float zb = 0.f;
#pragma unroll
                for (int k = 0; k < NSD; k++)
                    zb = fmaf(e[k], w1[(l * NSD + k) * NH + tid], zb);
                float t = fmaxf(fmaf(scale, zb, b1[l * NH + tid]), 0.f) *
                          w2[l * NH + tid];
#pragma unroll
                for (int o = 16; o; o >>= 1) t += __shfl_xor_sync(~0u, t, o);
                float acc = t + b2[l];
                // m=sigmoid(acc); m>0.5 <=> acc>0 -> factor 1 (exact);
                // else factor = 1-m = 1/(1+exp(acc))
                if (!(acc > 0.f)) scale *= 1.f / (1.f + expf(acc));
            }
            if (tid == 0) s_scale = scale;
        }
        __syncthreads();
        if (tid < NHID) g_F[v * NHID + tid] = s_scale * e1s[tid];
    }
}

// ---------------------------------------------------------------------------
// Kernel 2: warp per segment.
//   acc[64] = sum over the segment's nodes of F[atom]; then
//   out[g]  = relu(acc + pb1) @ pw2 + pb2
// Hot loop per node: SHFL broadcast + LDS.64 + add.rn.f32x2. No atomics.
// ---------------------------------------------------------------------------
typedef unsigned long long u64;
__device__ __forceinline__ void addx2(u64& acc, u64 f) {
    asm("add.rn.f32x2 %0, %0, %1;" : "+l"(acc) : "l"(f));
}

__global__ void __launch_bounds__(512)
main_kernel(const int* __restrict__ atoms,
            const float* __restrict__ pb1, const float* __restrict__ pw2,
            const float* __restrict__ pb2, float* __restrict__ out) {
    __shared__ float2 F2[NVOC * 32];      // F2[v*32+lane] = dims (2l, 2l+1)
    __shared__ float pb1s[NHID], pw2s[NHID];

    int tid = threadIdx.x;
    for (int i = tid; i < NVOC * 32; i += 512)
        F2[i] = reinterpret_cast<const float2*>(g_F)[i];
    if (tid < NHID) { pb1s[tid] = pb1[tid]; pw2s[tid] = pw2[tid]; }
    float pb2v = pb2[0];
    __syncthreads();

    int warp = tid >> 5, lane = tid & 31;
    int g = blockIdx.x * 16 + warp;
    int s = g_segstart[g], e = g_segstart[g + 1];

    const u64* F8 = reinterpret_cast<const u64*>(F2);
    u64 acc0 = 0ull, acc1 = 0ull;         // packed {0.f, 0.f}

    int nfull = (e - s) & ~31;
    int base  = s;
    for (; base < s + nfull; base += 32) {          // full 32-node blocks
        int a = atoms[base + lane];
#pragma unroll
        for (int k = 0; k < 32; k += 2) {
            int v0 = __shfl_sync(~0u, a, k);
            int v1 = __shfl_sync(~0u, a, k + 1);
            addx2(acc0, F8[v0 * 32 + lane]);
            addx2(acc1, F8[v1 * 32 + lane]);
        }
    }
    int rem = e - base;                              // tail (< 32 nodes)
    if (rem) {
        int a = (lane < rem) ? atoms[base + lane] : 0;
        for (int k = 0; k < rem; k++) {
            int v = __shfl_sync(~0u, a, k);
            if (k & 1) addx2(acc1, F8[v * 32 + lane]);
            else       addx2(acc0, F8[v * 32 + lane]);
        }
    }
    addx2(acc0, acc1);
    float ax = __uint_as_float((unsigned)(acc0 & 0xffffffffull));
    float ay = __uint_as_float((unsigned)(acc0 >> 32));

    float t = fmaf(fmaxf(ax + pb1s[2 * lane], 0.f), pw2s[2 * lane],
                   fmaxf(ay + pb1s[2 * lane + 1], 0.f) * pw2s[2 * lane + 1]);
#pragma unroll
    for (int o = 16; o; o >>= 1) t += __shfl_down_sync(~0u, t, o);
    if (lane == 0) out[g] = t + pb2v;
}

// ---------------------------------------------------------------------------
// Launch: 2 stream-ordered kernels.
// ---------------------------------------------------------------------------
extern "C" void kernel_launch(void* const* d_in, const int* in_sizes, int n_in,
                              void* d_out, int out_size) {
    const int*   atoms = (const int*)d_in[0];
    // d_in[1] pos        : UNUSED by reference
    // d_in[2] edge_index : UNUSED by reference
    const int*   batch = (const int*)d_in[3];
    const float* emb   = (const float*)d_in[4];
    const float* w1    = (const float*)d_in[5];
    const float* b1    = (const float*)d_in[6];
    const float* w2    = (const float*)d_in[7];
    const float* b2    = (const float*)d_in[8];
    const float* pw1   = (const float*)d_in[9];
    // d_in[10] pb1, d_in[11] pw2, d_in[12] pb2 used by main_kernel
    const float* pb1   = (const float*)d_in[10];
    const float* pw2   = (const float*)d_in[11];
    const float* pb2   = (const float*)d_in[12];
    int N = in_sizes[0];

    int nbb = (N + 1023) / 1024;          // 256 threads x 4 nodes per block
    prep_kernel<<<nbb + NVOC, 256>>>(batch, emb, w1, b1, w2, b2, pw1, N, nbb);
    main_kernel<<<NG / 16, 512>>>(atoms, pb1, pw2, pb2, (float*)d_out);
}

// round 14
// speedup vs baseline: 1.0022x; 1.0022x over previous
#include <cuda_runtime.h>

// Problem constants (fixed-shape problem)
#define NVOC 100     // vocab
#define NL   5       // gate layers
#define NH   32      // gate hidden (== warp size)
#define NSD  16      // s-dim
#define NG   8192    // segments
#define NEMB 128     // embedding dim
#define NHID 64      // EMB/2

// Scratch (__device__ globals; no allocations allowed).
// Both are fully rewritten every replay -> deterministic.
__device__ float g_F[NVOC * NHID];      // F[v] = scale[v] * (emb[v] @ pw1)
__device__ int   g_segstart[NG + 1];    // lower_bound of g in sorted batch

// ---------------------------------------------------------------------------
// Kernel 1 (fused, independent block ranges):
//   blocks [0, nbb)        : segment boundaries from sorted batch
//   blocks [nbb, nbb+NVOC) : F[v][j] = scale[v] * (emb[v] . pw1[:,j])
// ---------------------------------------------------------------------------
__global__ void __launch_bounds__(256)
prep_kernel(const int* __restrict__ batch,
            const float* __restrict__ emb, const float* __restrict__ w1,
            const float* __restrict__ b1,  const float* __restrict__ w2,
            const float* __restrict__ b2,  const float* __restrict__ pw1,
            int N, int nbb) {
    int bid = blockIdx.x;
    if (bid < nbb) {
        // ---- boundaries: seg_start[g] = first i with batch[i] >= g --------
        int i0 = (bid * 256 + threadIdx.x) * 4;   // this thread's 4 nodes
        if (i0 >= N) return;
        int b[5];
        if (i0 + 4 <= N) {
            int4 q = *reinterpret_cast<const int4*>(batch + i0);
            b[0] = q.x; b[1] = q.y; b[2] = q.z; b[3] = q.w;
        } else {
#pragma unroll
            for (int k = 0; k < 4; k++)
                b[k] = (i0 + k < N) ? batch[i0 + k] : 0;
        }
        b[4] = (i0 + 4 < N) ? batch[i0 + 4] : NG;   // sentinel past the end

        if (i0 == 0)
            for (int g = 0; g <= b[0]; g++) g_segstart[g] = 0;
#pragma unroll
        for (int k = 0; k < 4; k++) {
            if (i0 + k >= N) break;
            for (int g = b[k] + 1; g <= b[k + 1]; g++)
                g_segstart[g] = i0 + k + 1;
        }
    } else {
        // ---- F row for vocab v --------------------------------------------
        int v = bid - nbb;
        __shared__ float e1s[NHID];
        __shared__ float s_scale;
        int tid = threadIdx.x;

        if (tid < NHID) {                       // E1[v][j] = emb[v] . pw1[:,j]
            float a = 0.f;
#pragma unroll 8
            for (int d = 0; d < NEMB; d++)
                a = fmaf(emb[v * NEMB + d], pw1[d * NHID + tid], a);
            e1s[tid] = a;
        }
        if (tid < 32) {                         // gate cascade (vocab-only)
            float e[NSD];
#pragma unroll
            for (int k = 0; k < NSD; k++) e[k] = emb[v * NEMB + k];
            float scale = 1.f;
#pragma unroll
            for (int l = 0; l < NL; l++) {
                float zb = 0.f;
#pragma unroll
                for (int k = 0; k < NSD; k++)
                    zb = fmaf(e[k], w1[(l * NSD + k) * NH + tid], zb);
                float t = fmaxf(fmaf(scale, zb, b1[l * NH + tid]), 0.f) *
                          w2[l * NH + tid];
#pragma unroll
                for (int o = 16; o; o >>= 1) t += __shfl_xor_sync(~0u, t, o);
                float acc = t + b2[l];
                // m=sigmoid(acc); m>0.5 <=> acc>0 -> factor 1 (exact);
                // else factor = 1-m = 1/(1+exp(acc))
                if (!(acc > 0.f)) scale *= 1.f / (1.f + expf(acc));
            }
            if (tid == 0) s_scale = scale;
        }
        __syncthreads();
        if (tid < NHID) g_F[v * NHID + tid] = s_scale * e1s[tid];
    }
}

// ---------------------------------------------------------------------------
// Kernel 2: warp per segment.
//   acc[64] = sum over the segment's nodes of F[atom]; then
//   out[g]  = relu(acc + pb1) @ pw2 + pb2
// Hot loop per node: SHFL broadcast + LDS.64 + add.rn.f32x2. No atomics.
// ---------------------------------------------------------------------------
typedef unsigned long long u64;
__device__ __forceinline__ void addx2(u64& acc, u64 f) {
    asm("add.rn.f32x2 %0, %0, %1;" : "+l"(acc) : "l"(f));
}

__global__ void __launch_bounds__(512)
main_kernel(const int* __restrict__ atoms,
            const float* __restrict__ pb1, const float* __restrict__ pw2,
            const float* __restrict__ pb2, float* __restrict__ out) {
    __shared__ float2 F2[NVOC * 32];      // F2[v*32+lane] = dims (2l, 2l+1)
    __shared__ float pb1s[NHID], pw2s[NHID];

    int tid = threadIdx.x;
    for (int i = tid; i < NVOC * 32; i += 512)
        F2[i] = reinterpret_cast<const float2*>(g_F)[i];
    if (tid < NHID) { pb1s[tid] = pb1[tid]; pw2s[tid] = pw2[tid]; }
    float pb2v = pb2[0];
    __syncthreads();

    int warp = tid >> 5, lane = tid & 31;
    int g = blockIdx.x * 16 + warp;
    int s = g_segstart[g], e = g_segstart[g + 1];

    const u64* F8 = reinterpret_cast<const u64*>(F2);
    u64 acc0 = 0ull, acc1 = 0ull;         // packed {0.f, 0.f}

    int nfull = (e - s) & ~31;
    int base  = s;
    for (; base < s + nfull; base += 32) {          // full 32-node blocks
        int a = atoms[base + lane];
#pragma unroll
        for (int k = 0; k < 32; k += 2) {
            int v0 = __shfl_sync(~0u, a, k);
            int v1 = __shfl_sync(~0u, a, k + 1);
            addx2(acc0, F8[v0 * 32 + lane]);
            addx2(acc1, F8[v1 * 32 + lane]);
        }
    }
    int rem = e - base;                              // tail (< 32 nodes)
    if (rem) {
        int a = (lane < rem) ? atoms[base + lane] : 0;
        for (int k = 0; k < rem; k++) {
            int v = __shfl_sync(~0u, a, k);
            if (k & 1) addx2(acc1, F8[v * 32 + lane]);
            else       addx2(acc0, F8[v * 32 + lane]);
        }
    }
    addx2(acc0, acc1);
    float ax = __uint_as_float((unsigned)(acc0 & 0xffffffffull));
    float ay = __uint_as_float((unsigned)(acc0 >> 32));

    float t = fmaf(fmaxf(ax + pb1s[2 * lane], 0.f), pw2s[2 * lane],
                   fmaxf(ay + pb1s[2 * lane + 1], 0.f) * pw2s[2 * lane + 1]);
#pragma unroll
    for (int o = 16; o; o >>= 1) t += __shfl_down_sync(~0u, t, o);
    if (lane == 0) out[g] = t + pb2v;
}

// ---------------------------------------------------------------------------
// Launch: 2 stream-ordered kernels.
// ---------------------------------------------------------------------------
extern "C" void kernel_launch(void* const* d_in, const int* in_sizes, int n_in,
                              void* d_out, int out_size) {
    const int*   atoms = (const int*)d_in[0];
    // d_in[1] pos        : UNUSED by reference
    // d_in[2] edge_index : UNUSED by reference
    const int*   batch = (const int*)d_in[3];
    const float* emb   = (const float*)d_in[4];
    const float* w1    = (const float*)d_in[5];
    const float* b1    = (const float*)d_in[6];
    const float* w2    = (const float*)d_in[7];
    const float* b2    = (const float*)d_in[8];
    const float* pw1   = (const float*)d_in[9];
    // d_in[10] pb1, d_in[11] pw2, d_in[12] pb2 used by main_kernel
    const float* pb1   = (const float*)d_in[10];
    const float* pw2   = (const float*)d_in[11];
    const float* pb2   = (const float*)d_in[12];
    int N = in_sizes[0];

    int nbb = (N + 1023) / 1024;          // 256 threads x 4 nodes per block
    prep_kernel<<<nbb + NVOC, 256>>>(batch, emb, w1, b1, w2, b2, pw1, N, nbb);
    main_kernel<<<NG / 16, 512>>>(atoms, pb1, pw2, pb2, (float*)d_out);
}